// round 3
// baseline (speedup 1.0000x reference)
#include <cuda_runtime.h>
#include <math.h>

// Problem constants
#define B_    4
#define L_    2052
#define C_    1024
#define H_    16
#define D_    64
#define NREG_ 4
#define M_    (B_ * L_)      // 8208 rows
#define LP_   (L_ - NREG_)   // 2048 rope positions

// ---------------- scratch (device globals, no allocations) ----------------
__device__ float g_qkv[M_ * 3 * C_];          // ~100.9 MB
__device__ float g_q[B_ * H_ * L_ * D_];
__device__ float g_k[B_ * H_ * L_ * D_];
__device__ float g_v[B_ * H_ * L_ * D_];
__device__ float g_attn[M_ * C_];
__device__ float g_ln[M_ * C_];

// =====================================================================
// SGEMM with bias: C[M,N] = A[M,K] @ B[K,N] + bias[N]
// 128x128 tile, Kc=16, 256 threads, 8x8 micro-tile.
// Requires: N % 128 == 0, K % 16 == 0 (true here: N in {3072,1024}, K=1024).
// =====================================================================
__global__ __launch_bounds__(256) void sgemm_bias_kernel(
    const float* __restrict__ A, const float* __restrict__ Bm,
    const float* __restrict__ bias, float* __restrict__ Cm,
    int M, int N, int K)
{
    __shared__ float As[16][132];   // k-major (transposed), padded
    __shared__ float Bs[16][128];

    const int tid = threadIdx.x;
    const int ti = tid >> 4;      // 0..15
    const int tj = tid & 15;      // 0..15
    const int m0 = blockIdx.y * 128;
    const int n0 = blockIdx.x * 128;

    float acc[8][8];
#pragma unroll
    for (int a = 0; a < 8; a++)
#pragma unroll
        for (int b = 0; b < 8; b++) acc[a][b] = 0.0f;

    for (int k0 = 0; k0 < K; k0 += 16) {
        // ---- load A tile (128 rows x 16 k), store transposed ----
#pragma unroll
        for (int i = 0; i < 2; i++) {
            int f = tid + i * 256;
            int r = f >> 2;            // 0..127
            int c4 = (f & 3) * 4;      // 0,4,8,12
            float4 v = make_float4(0.f, 0.f, 0.f, 0.f);
            int m = m0 + r;
            if (m < M) v = *(const float4*)&A[(size_t)m * K + k0 + c4];
            As[c4 + 0][r] = v.x;
            As[c4 + 1][r] = v.y;
            As[c4 + 2][r] = v.z;
            As[c4 + 3][r] = v.w;
        }
        // ---- load B tile (16 k x 128 n) ----
#pragma unroll
        for (int i = 0; i < 2; i++) {
            int f = tid + i * 256;
            int r = f >> 5;            // 0..15
            int c4 = (f & 31) * 4;     // 0..124
            *(float4*)&Bs[r][c4] = *(const float4*)&Bm[(size_t)(k0 + r) * N + n0 + c4];
        }
        __syncthreads();

#pragma unroll
        for (int k = 0; k < 16; k++) {
            float4 aA = *(float4*)&As[k][8 * ti];
            float4 aB = *(float4*)&As[k][8 * ti + 4];
            float4 bA = *(float4*)&Bs[k][8 * tj];
            float4 bB = *(float4*)&Bs[k][8 * tj + 4];
            float av[8] = {aA.x, aA.y, aA.z, aA.w, aB.x, aB.y, aB.z, aB.w};
            float bv[8] = {bA.x, bA.y, bA.z, bA.w, bB.x, bB.y, bB.z, bB.w};
#pragma unroll
            for (int a = 0; a < 8; a++)
#pragma unroll
                for (int b = 0; b < 8; b++)
                    acc[a][b] += av[a] * bv[b];
        }
        __syncthreads();
    }

    // ---- epilogue: bias + store ----
    float4 bz0 = *(const float4*)&bias[n0 + 8 * tj];
    float4 bz1 = *(const float4*)&bias[n0 + 8 * tj + 4];
#pragma unroll
    for (int a = 0; a < 8; a++) {
        int m = m0 + 8 * ti + a;
        if (m < M) {
            float4 o0, o1;
            o0.x = acc[a][0] + bz0.x; o0.y = acc[a][1] + bz0.y;
            o0.z = acc[a][2] + bz0.z; o0.w = acc[a][3] + bz0.w;
            o1.x = acc[a][4] + bz1.x; o1.y = acc[a][5] + bz1.y;
            o1.z = acc[a][6] + bz1.z; o1.w = acc[a][7] + bz1.w;
            *(float4*)&Cm[(size_t)m * N + n0 + 8 * tj]     = o0;
            *(float4*)&Cm[(size_t)m * N + n0 + 8 * tj + 4] = o1;
        }
    }
}

// =====================================================================
// RoPE + split qkv -> g_q, g_k, g_v in (B,H,L,D) layout.
// =====================================================================
__global__ __launch_bounds__(256) void rope_split_kernel(
    const float* __restrict__ qkv, const float* __restrict__ rope)
{
    int idx = blockIdx.x * blockDim.x + threadIdx.x;
    const int total = B_ * H_ * L_ * 32;
    if (idx >= total) return;

    int dp = idx & 31;
    int t  = idx >> 5;
    int l  = t % L_;
    int bh = t / L_;                 // b*H + h
    int h  = bh & (H_ - 1);
    int bb = bh >> 4;

    size_t base = ((size_t)(bb * L_ + l)) * (3 * C_) + h * D_;
    float q1 = qkv[base + dp],          q2 = qkv[base + dp + 32];
    float k1 = qkv[base + C_ + dp],     k2 = qkv[base + C_ + dp + 32];
    float v1 = qkv[base + 2 * C_ + dp], v2 = qkv[base + 2 * C_ + dp + 32];

    if (l >= NREG_) {
        int p = l - NREG_;
        const float* cosr = rope + (size_t)p * D_;
        const float* sinr = rope + (size_t)LP_ * D_ + (size_t)p * D_;
        float c1 = cosr[dp], c2 = cosr[dp + 32];
        float s1 = sinr[dp], s2 = sinr[dp + 32];
        float nq1 = q1 * c1 - q2 * s1;
        float nq2 = q2 * c2 + q1 * s2;
        float nk1 = k1 * c1 - k2 * s1;
        float nk2 = k2 * c2 + k1 * s2;
        q1 = nq1; q2 = nq2; k1 = nk1; k2 = nk2;
    }

    size_t dst = ((size_t)bh * L_ + l) * D_;
    g_q[dst + dp] = q1; g_q[dst + dp + 32] = q2;
    g_k[dst + dp] = k1; g_k[dst + dp + 32] = k2;
    g_v[dst + dp] = v1; g_v[dst + dp + 32] = v2;
}

// =====================================================================
// Flash attention (fp32, online softmax).
// Block = (q-tile of 64) x (one b,h). 256 threads, 4x4 micro-tiles.
// =====================================================================
__global__ __launch_bounds__(256) void attn_kernel(
    const float* __restrict__ Q, const float* __restrict__ K,
    const float* __restrict__ V, float* __restrict__ Out)
{
    __shared__ float Qs[64][64];   // swizzled: chunk c stored at c ^ (row>>2)
    __shared__ float Ks[64][64];   // swizzled; reused for P after S phase
    __shared__ float Vs[64][64];   // plain

    const int bh = blockIdx.y;
    const int q0 = blockIdx.x * 64;
    const float* Qp = Q + (size_t)bh * L_ * D_;
    const float* Kp = K + (size_t)bh * L_ * D_;
    const float* Vp = V + (size_t)bh * L_ * D_;

    const int tid = threadIdx.x;
    const int ti = tid >> 4;
    const int tj = tid & 15;

    // ---- load Q tile (swizzled), zero-fill OOB rows ----
#pragma unroll
    for (int i = 0; i < 4; i++) {
        int f = tid + i * 256;
        int r = f >> 4;
        int c = f & 15;
        int sw = c ^ (r >> 2);
        float4 v = make_float4(0.f, 0.f, 0.f, 0.f);
        if (q0 + r < L_) v = *(const float4*)&Qp[(size_t)(q0 + r) * D_ + c * 4];
        *(float4*)&Qs[r][sw * 4] = v;
    }

    float mrow[4], lrow[4], acc[4][4];
#pragma unroll
    for (int a = 0; a < 4; a++) {
        mrow[a] = -1e30f;
        lrow[a] = 0.0f;
#pragma unroll
        for (int b = 0; b < 4; b++) acc[a][b] = 0.0f;
    }
    __syncthreads();

    const float scale = 0.125f;   // 1/sqrt(64)
    const int KT = (L_ + 63) >> 6; // 33

    for (int kt = 0; kt < KT; kt++) {
        const int k0 = kt * 64;
#pragma unroll
        for (int i = 0; i < 4; i++) {
            int f = tid + i * 256;
            int r = f >> 4;
            int c = f & 15;
            int sw = c ^ (r >> 2);
            float4 kv = make_float4(0.f, 0.f, 0.f, 0.f);
            float4 vv = make_float4(0.f, 0.f, 0.f, 0.f);
            if (k0 + r < L_) {
                kv = *(const float4*)&Kp[(size_t)(k0 + r) * D_ + c * 4];
                vv = *(const float4*)&Vp[(size_t)(k0 + r) * D_ + c * 4];
            }
            *(float4*)&Ks[r][sw * 4] = kv;
            *(float4*)&Vs[r][c * 4] = vv;
        }
        __syncthreads();

        // ---- S = Q K^T ----
        float s[4][4];
#pragma unroll
        for (int a = 0; a < 4; a++)
#pragma unroll
            for (int b = 0; b < 4; b++) s[a][b] = 0.0f;

#pragma unroll
        for (int d4 = 0; d4 < 16; d4++) {
            float4 q4[4], k4[4];
#pragma unroll
            for (int a = 0; a < 4; a++) q4[a] = *(float4*)&Qs[4 * ti + a][(d4 ^ ti) * 4];
#pragma unroll
            for (int b = 0; b < 4; b++) k4[b] = *(float4*)&Ks[4 * tj + b][(d4 ^ tj) * 4];
#pragma unroll
            for (int a = 0; a < 4; a++)
#pragma unroll
                for (int b = 0; b < 4; b++)
                    s[a][b] += q4[a].x * k4[b].x + q4[a].y * k4[b].y +
                               q4[a].z * k4[b].z + q4[a].w * k4[b].w;
        }

        const bool partial = (k0 + 64 > L_);
#pragma unroll
        for (int a = 0; a < 4; a++)
#pragma unroll
            for (int b = 0; b < 4; b++) {
                float sv = s[a][b] * scale;
                if (partial && (k0 + 4 * tj + b >= L_)) sv = -1e30f;
                s[a][b] = sv;
            }

        // ---- online softmax update ----
        float corr[4];
#pragma unroll
        for (int a = 0; a < 4; a++) {
            float rmax = fmaxf(fmaxf(s[a][0], s[a][1]), fmaxf(s[a][2], s[a][3]));
#pragma unroll
            for (int off = 8; off > 0; off >>= 1)
                rmax = fmaxf(rmax, __shfl_xor_sync(0xffffffffu, rmax, off));
            float mnew = fmaxf(mrow[a], rmax);
            corr[a] = __expf(mrow[a] - mnew);
            mrow[a] = mnew;

            float t = 0.0f;
#pragma unroll
            for (int b = 0; b < 4; b++) {
                float p = __expf(s[a][b] - mnew);
                s[a][b] = p;
                t += p;
            }
#pragma unroll
            for (int off = 8; off > 0; off >>= 1)
                t += __shfl_xor_sync(0xffffffffu, t, off);
            lrow[a] = lrow[a] * corr[a] + t;
#pragma unroll
            for (int b = 0; b < 4; b++) acc[a][b] *= corr[a];
        }

        __syncthreads();   // everyone done reading Ks (K data)
#pragma unroll
        for (int a = 0; a < 4; a++)
#pragma unroll
            for (int b = 0; b < 4; b++)
                Ks[4 * ti + a][((tj ^ ti) * 4) + b] = s[a][b];
        __syncthreads();

        // ---- O += P @ V ----
#pragma unroll
        for (int j4 = 0; j4 < 16; j4++) {
            float4 p4[4], v4[4];
#pragma unroll
            for (int a = 0; a < 4; a++) p4[a] = *(float4*)&Ks[4 * ti + a][(j4 ^ ti) * 4];
#pragma unroll
            for (int jj = 0; jj < 4; jj++) v4[jj] = *(float4*)&Vs[4 * j4 + jj][4 * tj];
#pragma unroll
            for (int a = 0; a < 4; a++) {
                acc[a][0] += p4[a].x * v4[0].x + p4[a].y * v4[1].x + p4[a].z * v4[2].x + p4[a].w * v4[3].x;
                acc[a][1] += p4[a].x * v4[0].y + p4[a].y * v4[1].y + p4[a].z * v4[2].y + p4[a].w * v4[3].y;
                acc[a][2] += p4[a].x * v4[0].z + p4[a].y * v4[1].z + p4[a].z * v4[2].z + p4[a].w * v4[3].z;
                acc[a][3] += p4[a].x * v4[0].w + p4[a].y * v4[1].w + p4[a].z * v4[2].w + p4[a].w * v4[3].w;
            }
        }
        __syncthreads();
    }

    // ---- epilogue ----
    const int bb = bh >> 4;
    const int h = bh & (H_ - 1);
#pragma unroll
    for (int a = 0; a < 4; a++) {
        int row = q0 + 4 * ti + a;
        if (row < L_) {
            float inv = 1.0f / lrow[a];
            float4 o;
            o.x = acc[a][0] * inv;
            o.y = acc[a][1] * inv;
            o.z = acc[a][2] * inv;
            o.w = acc[a][3] * inv;
            *(float4*)&Out[((size_t)(bb * L_ + row)) * C_ + h * D_ + 4 * tj] = o;
        }
    }
}

// =====================================================================
// LayerNorm over last dim (1024). One block (256 threads) per row.
// =====================================================================
__global__ __launch_bounds__(256) void ln_kernel(
    const float* __restrict__ in, const float* __restrict__ gamma,
    const float* __restrict__ beta, float* __restrict__ out)
{
    __shared__ float red[16];
    const int row = blockIdx.x;
    const float* xp = in + (size_t)row * C_;
    const int c = threadIdx.x * 4;

    float4 v = *(const float4*)&xp[c];
    float s  = v.x + v.y + v.z + v.w;
    float sq = v.x * v.x + v.y * v.y + v.z * v.z + v.w * v.w;

#pragma unroll
    for (int off = 16; off > 0; off >>= 1) {
        s  += __shfl_xor_sync(0xffffffffu, s, off);
        sq += __shfl_xor_sync(0xffffffffu, sq, off);
    }
    int wid = threadIdx.x >> 5, lid = threadIdx.x & 31;
    if (lid == 0) { red[wid] = s; red[8 + wid] = sq; }
    __syncthreads();

    float ts = 0.f, tq = 0.f;
#pragma unroll
    for (int i = 0; i < 8; i++) { ts += red[i]; tq += red[8 + i]; }

    float mu   = ts * (1.0f / C_);
    float var  = tq * (1.0f / C_) - mu * mu;
    float rstd = rsqrtf(var + 1e-5f);

    float4 g = *(const float4*)&gamma[c];
    float4 b = *(const float4*)&beta[c];
    float4 o;
    o.x = (v.x - mu) * rstd * g.x + b.x;
    o.y = (v.y - mu) * rstd * g.y + b.y;
    o.z = (v.z - mu) * rstd * g.z + b.z;
    o.w = (v.w - mu) * rstd * g.w + b.w;
    *(float4*)&out[(size_t)row * C_ + c] = o;
}

// =====================================================================
// host side
// =====================================================================
static float* sym_addr_qkv()  { void* p = 0; cudaGetSymbolAddress(&p, g_qkv);  return (float*)p; }
static float* sym_addr_q()    { void* p = 0; cudaGetSymbolAddress(&p, g_q);    return (float*)p; }
static float* sym_addr_k()    { void* p = 0; cudaGetSymbolAddress(&p, g_k);    return (float*)p; }
static float* sym_addr_v()    { void* p = 0; cudaGetSymbolAddress(&p, g_v);    return (float*)p; }
static float* sym_addr_attn() { void* p = 0; cudaGetSymbolAddress(&p, g_attn); return (float*)p; }
static float* sym_addr_ln()   { void* p = 0; cudaGetSymbolAddress(&p, g_ln);   return (float*)p; }

extern "C" void kernel_launch(void* const* d_in, const int* in_sizes, int n_in,
                              void* d_out, int out_size)
{
    const float* x     = (const float*)d_in[0];
    const float* rope  = (const float*)d_in[1];
    const float* Wqkv  = (const float*)d_in[2];
    const float* bqkv  = (const float*)d_in[3];
    const float* Wproj = (const float*)d_in[4];
    const float* bproj = (const float*)d_in[5];
    const float* gamma = (const float*)d_in[6];
    const float* beta  = (const float*)d_in[7];
    float* out = (float*)d_out;

    float* qkv = sym_addr_qkv();
    float* q   = sym_addr_q();
    float* k   = sym_addr_k();
    float* v   = sym_addr_v();
    float* att = sym_addr_attn();
    float* ln  = sym_addr_ln();

    // 1) QKV GEMM: (8208,1024) @ (1024,3072) + bias
    {
        dim3 grid(3 * C_ / 128, (M_ + 127) / 128);
        sgemm_bias_kernel<<<grid, 256>>>(x, Wqkv, bqkv, qkv, M_, 3 * C_, C_);
    }
    // 2) RoPE + split into (B,H,L,D)
    {
        int total = B_ * H_ * L_ * 32;
        rope_split_kernel<<<(total + 255) / 256, 256>>>(qkv, rope);
    }
    // 3) Flash attention
    {
        dim3 grid((L_ + 63) / 64, B_ * H_);
        attn_kernel<<<grid, 256>>>(q, k, v, att);
    }
    // 4) LayerNorm
    ln_kernel<<<M_, 256>>>(att, gamma, beta, ln);
    // 5) Proj GEMM: (8208,1024) @ (1024,1024) + bias
    {
        dim3 grid(C_ / 128, (M_ + 127) / 128);
        sgemm_bias_kernel<<<grid, 256>>>(ln, Wproj, bproj, out, M_, C_, C_);
    }
}

// round 8
// speedup vs baseline: 1.3019x; 1.3019x over previous
#include <cuda_runtime.h>
#include <math.h>
#include <stdint.h>

// Problem constants
#define B_    4
#define L_    2052
#define C_    1024
#define H_    16
#define D_    64
#define NREG_ 4
#define M_    (B_ * L_)      // 8208 rows
#define LP_   (L_ - NREG_)   // 2048 rope positions

// ---------------- scratch (device globals, no allocations) ----------------
__device__ float g_qkv[M_ * 3 * C_];
__device__ float g_q[B_ * H_ * L_ * D_];
__device__ float g_k[B_ * H_ * L_ * D_];
__device__ float g_v[B_ * H_ * L_ * D_];
__device__ float g_attn[M_ * C_];
__device__ float g_ln[M_ * C_];

// ---------------- tf32 helpers ----------------
__device__ __forceinline__ uint32_t f2tf32(float x) {
    uint32_t r;
    asm("cvt.rna.tf32.f32 %0, %1;" : "=r"(r) : "f"(x));
    return r;
}

// 3xTF32 split: x ~= hi + lo, both tf32-representable.
__device__ __forceinline__ void tf32_split(float x, uint32_t* hi, uint32_t* lo) {
    uint32_t h = f2tf32(x);
    float hf = __uint_as_float(h);
    *hi = h;
    *lo = f2tf32(x - hf);
}

__device__ __forceinline__ void mma_tf32(float* d, const uint32_t* a,
                                         const uint32_t* b, const float* c) {
    asm volatile(
        "mma.sync.aligned.m16n8k8.row.col.f32.tf32.tf32.f32 "
        "{%0,%1,%2,%3}, {%4,%5,%6,%7}, {%8,%9}, {%10,%11,%12,%13};\n"
        : "=f"(d[0]), "=f"(d[1]), "=f"(d[2]), "=f"(d[3])
        : "r"(a[0]), "r"(a[1]), "r"(a[2]), "r"(a[3]),
          "r"(b[0]), "r"(b[1]),
          "f"(c[0]), "f"(c[1]), "f"(c[2]), "f"(c[3]));
}

// =====================================================================
// 3xTF32 tensor-core GEMM with bias: C[M,N] = A[M,K] @ B[K,N] + bias[N]
// 128x128 block tile, BK=32, 256 threads (8 warps, 2x4), warp tile 64x32.
// Dynamic smem: As hi/lo [128][36], Bs hi/lo [32][136]  (71680 B).
// =====================================================================
#define GA_STR 36
#define GB_STR 136
#define G_SMEM_BYTES ((2 * 128 * GA_STR + 2 * 32 * GB_STR) * 4)

__global__ __launch_bounds__(256) void gemm_tf32x3_bias_kernel(
    const float* __restrict__ A, const float* __restrict__ Bm,
    const float* __restrict__ bias, float* __restrict__ Cm,
    int M, int N, int K)
{
    extern __shared__ uint32_t gsm[];
    uint32_t* As_hi = gsm;
    uint32_t* As_lo = As_hi + 128 * GA_STR;
    uint32_t* Bs_hi = As_lo + 128 * GA_STR;
    uint32_t* Bs_lo = Bs_hi + 32 * GB_STR;

    const int tid  = threadIdx.x;
    const int lane = tid & 31;
    const int warp = tid >> 5;
    const int wm   = warp & 1;
    const int wn   = warp >> 1;
    const int g    = lane >> 2;
    const int t    = lane & 3;
    const int m0   = blockIdx.y * 128;
    const int n0   = blockIdx.x * 128;

    float acc[4][4][4];
#pragma unroll
    for (int i = 0; i < 4; i++)
#pragma unroll
        for (int j = 0; j < 4; j++)
#pragma unroll
            for (int r = 0; r < 4; r++) acc[i][j][r] = 0.0f;

    for (int k0 = 0; k0 < K; k0 += 32) {
        // ---- stage A tile (128x32) hi/lo ----
#pragma unroll
        for (int i = 0; i < 4; i++) {
            int f  = tid + i * 256;
            int r  = f >> 3;
            int c4 = (f & 7) * 4;
            float4 v = make_float4(0.f, 0.f, 0.f, 0.f);
            if (m0 + r < M) v = *(const float4*)&A[(size_t)(m0 + r) * K + k0 + c4];
            uint32_t h, l;
            tf32_split(v.x, &h, &l); As_hi[r * GA_STR + c4 + 0] = h; As_lo[r * GA_STR + c4 + 0] = l;
            tf32_split(v.y, &h, &l); As_hi[r * GA_STR + c4 + 1] = h; As_lo[r * GA_STR + c4 + 1] = l;
            tf32_split(v.z, &h, &l); As_hi[r * GA_STR + c4 + 2] = h; As_lo[r * GA_STR + c4 + 2] = l;
            tf32_split(v.w, &h, &l); As_hi[r * GA_STR + c4 + 3] = h; As_lo[r * GA_STR + c4 + 3] = l;
        }
        // ---- stage B tile (32x128) hi/lo ----
#pragma unroll
        for (int i = 0; i < 4; i++) {
            int f  = tid + i * 256;
            int r  = f >> 5;
            int c4 = (f & 31) * 4;
            float4 v = *(const float4*)&Bm[(size_t)(k0 + r) * N + n0 + c4];
            uint32_t h, l;
            tf32_split(v.x, &h, &l); Bs_hi[r * GB_STR + c4 + 0] = h; Bs_lo[r * GB_STR + c4 + 0] = l;
            tf32_split(v.y, &h, &l); Bs_hi[r * GB_STR + c4 + 1] = h; Bs_lo[r * GB_STR + c4 + 1] = l;
            tf32_split(v.z, &h, &l); Bs_hi[r * GB_STR + c4 + 2] = h; Bs_lo[r * GB_STR + c4 + 2] = l;
            tf32_split(v.w, &h, &l); Bs_hi[r * GB_STR + c4 + 3] = h; Bs_lo[r * GB_STR + c4 + 3] = l;
        }
        __syncthreads();

#pragma unroll
        for (int kk = 0; kk < 32; kk += 8) {
            uint32_t ah[4][4], al[4][4], bh[4][2], bl[4][2];
#pragma unroll
            for (int i = 0; i < 4; i++) {
                int rb = wm * 64 + i * 16;
                ah[i][0] = As_hi[(rb + g)     * GA_STR + kk + t];
                ah[i][1] = As_hi[(rb + g + 8) * GA_STR + kk + t];
                ah[i][2] = As_hi[(rb + g)     * GA_STR + kk + t + 4];
                ah[i][3] = As_hi[(rb + g + 8) * GA_STR + kk + t + 4];
                al[i][0] = As_lo[(rb + g)     * GA_STR + kk + t];
                al[i][1] = As_lo[(rb + g + 8) * GA_STR + kk + t];
                al[i][2] = As_lo[(rb + g)     * GA_STR + kk + t + 4];
                al[i][3] = As_lo[(rb + g + 8) * GA_STR + kk + t + 4];
            }
#pragma unroll
            for (int j = 0; j < 4; j++) {
                int nb = wn * 32 + j * 8;
                bh[j][0] = Bs_hi[(kk + t)     * GB_STR + nb + g];
                bh[j][1] = Bs_hi[(kk + t + 4) * GB_STR + nb + g];
                bl[j][0] = Bs_lo[(kk + t)     * GB_STR + nb + g];
                bl[j][1] = Bs_lo[(kk + t + 4) * GB_STR + nb + g];
            }
#pragma unroll
            for (int i = 0; i < 4; i++)
#pragma unroll
                for (int j = 0; j < 4; j++) {
                    mma_tf32(acc[i][j], al[i], bh[j], acc[i][j]);
                    mma_tf32(acc[i][j], ah[i], bl[j], acc[i][j]);
                    mma_tf32(acc[i][j], ah[i], bh[j], acc[i][j]);
                }
        }
        __syncthreads();
    }

#pragma unroll
    for (int i = 0; i < 4; i++) {
        int row0 = m0 + wm * 64 + i * 16 + g;
#pragma unroll
        for (int j = 0; j < 4; j++) {
            int col = n0 + wn * 32 + j * 8 + 2 * t;
            float b0 = bias[col], b1 = bias[col + 1];
            if (row0 < M) {
                float2 o = make_float2(acc[i][j][0] + b0, acc[i][j][1] + b1);
                *(float2*)&Cm[(size_t)row0 * N + col] = o;
            }
            if (row0 + 8 < M) {
                float2 o = make_float2(acc[i][j][2] + b0, acc[i][j][3] + b1);
                *(float2*)&Cm[(size_t)(row0 + 8) * N + col] = o;
            }
        }
    }
}

// =====================================================================
// RoPE + split qkv -> g_q, g_k, g_v in (B,H,L,D) layout.
// =====================================================================
__global__ __launch_bounds__(256) void rope_split_kernel(
    const float* __restrict__ qkv, const float* __restrict__ rope)
{
    int idx = blockIdx.x * blockDim.x + threadIdx.x;
    const int total = B_ * H_ * L_ * 32;
    if (idx >= total) return;

    int dp = idx & 31;
    int t  = idx >> 5;
    int l  = t % L_;
    int bh = t / L_;
    int h  = bh & (H_ - 1);
    int bb = bh >> 4;

    size_t base = ((size_t)(bb * L_ + l)) * (3 * C_) + h * D_;
    float q1 = qkv[base + dp],          q2 = qkv[base + dp + 32];
    float k1 = qkv[base + C_ + dp],     k2 = qkv[base + C_ + dp + 32];
    float v1 = qkv[base + 2 * C_ + dp], v2 = qkv[base + 2 * C_ + dp + 32];

    if (l >= NREG_) {
        int p = l - NREG_;
        const float* cosr = rope + (size_t)p * D_;
        const float* sinr = rope + (size_t)LP_ * D_ + (size_t)p * D_;
        float c1 = cosr[dp], c2 = cosr[dp + 32];
        float s1 = sinr[dp], s2 = sinr[dp + 32];
        float nq1 = q1 * c1 - q2 * s1;
        float nq2 = q2 * c2 + q1 * s2;
        float nk1 = k1 * c1 - k2 * s1;
        float nk2 = k2 * c2 + k1 * s2;
        q1 = nq1; q2 = nq2; k1 = nk1; k2 = nk2;
    }

    size_t dst = ((size_t)bh * L_ + l) * D_;
    g_q[dst + dp] = q1; g_q[dst + dp + 32] = q2;
    g_k[dst + dp] = k1; g_k[dst + dp + 32] = k2;
    g_v[dst + dp] = v1; g_v[dst + dp + 32] = v2;
}

// =====================================================================
// Flash attention, 3xTF32 tensor cores (fp32-accurate).
// Block: 128 q-rows x one (b,h). 8 warps, each owns m16 strip.
// Dynamic smem (hi/lo pairs):
//   Ks [64][68]x2, Vs [64][72]x2, Ps [128][68]x2   = 141312 B
// =====================================================================
#define AT_KS_STRIDE 68
#define AT_VS_STRIDE 72
#define AT_PS_STRIDE 68
#define AT_SMEM_U32  (2 * (64 * AT_KS_STRIDE + 64 * AT_VS_STRIDE + 128 * AT_PS_STRIDE))

__global__ __launch_bounds__(256) void attn_tc_kernel(
    const float* __restrict__ Q, const float* __restrict__ K,
    const float* __restrict__ V, float* __restrict__ Out)
{
    extern __shared__ uint32_t sm[];
    uint32_t* Ks_hi = sm;
    uint32_t* Ks_lo = Ks_hi + 64 * AT_KS_STRIDE;
    uint32_t* Vs_hi = Ks_lo + 64 * AT_KS_STRIDE;
    uint32_t* Vs_lo = Vs_hi + 64 * AT_VS_STRIDE;
    uint32_t* Ps_hi = Vs_lo + 64 * AT_VS_STRIDE;
    uint32_t* Ps_lo = Ps_hi + 128 * AT_PS_STRIDE;

    const int bh = blockIdx.y;
    const int q0 = blockIdx.x * 128;
    const float* Qp = Q + (size_t)bh * L_ * D_;
    const float* Kp = K + (size_t)bh * L_ * D_;
    const float* Vp = V + (size_t)bh * L_ * D_;

    const int tid  = threadIdx.x;
    const int lane = tid & 31;
    const int warp = tid >> 5;
    const int g    = lane >> 2;
    const int t    = lane & 3;
    const int wrow = warp * 16;

    // ---- stage Q tile (128x64) hi/lo into Ps ----
#pragma unroll
    for (int i = 0; i < 8; i++) {
        int f = tid + i * 256;
        int r = f >> 4;
        int d4 = (f & 15) * 4;
        float4 v = make_float4(0.f, 0.f, 0.f, 0.f);
        if (q0 + r < L_) v = *(const float4*)&Qp[(size_t)(q0 + r) * D_ + d4];
        uint32_t h, l;
        tf32_split(v.x, &h, &l); Ps_hi[r * AT_PS_STRIDE + d4 + 0] = h; Ps_lo[r * AT_PS_STRIDE + d4 + 0] = l;
        tf32_split(v.y, &h, &l); Ps_hi[r * AT_PS_STRIDE + d4 + 1] = h; Ps_lo[r * AT_PS_STRIDE + d4 + 1] = l;
        tf32_split(v.z, &h, &l); Ps_hi[r * AT_PS_STRIDE + d4 + 2] = h; Ps_lo[r * AT_PS_STRIDE + d4 + 2] = l;
        tf32_split(v.w, &h, &l); Ps_hi[r * AT_PS_STRIDE + d4 + 3] = h; Ps_lo[r * AT_PS_STRIDE + d4 + 3] = l;
    }
    __syncthreads();

    // ---- preload Q fragments hi/lo (m16 x k64 = 8 k-steps) ----
    uint32_t qh[8][4], ql[8][4];
#pragma unroll
    for (int kk = 0; kk < 8; kk++) {
        qh[kk][0] = Ps_hi[(wrow + g)     * AT_PS_STRIDE + 8 * kk + t];
        qh[kk][1] = Ps_hi[(wrow + g + 8) * AT_PS_STRIDE + 8 * kk + t];
        qh[kk][2] = Ps_hi[(wrow + g)     * AT_PS_STRIDE + 8 * kk + t + 4];
        qh[kk][3] = Ps_hi[(wrow + g + 8) * AT_PS_STRIDE + 8 * kk + t + 4];
        ql[kk][0] = Ps_lo[(wrow + g)     * AT_PS_STRIDE + 8 * kk + t];
        ql[kk][1] = Ps_lo[(wrow + g + 8) * AT_PS_STRIDE + 8 * kk + t];
        ql[kk][2] = Ps_lo[(wrow + g)     * AT_PS_STRIDE + 8 * kk + t + 4];
        ql[kk][3] = Ps_lo[(wrow + g + 8) * AT_PS_STRIDE + 8 * kk + t + 4];
    }
    __syncthreads();   // Ps free for P tiles

    float m0r = -1e30f, m1r = -1e30f, l0 = 0.f, l1 = 0.f;
    float oacc[8][4];
#pragma unroll
    for (int n = 0; n < 8; n++)
#pragma unroll
        for (int r = 0; r < 4; r++) oacc[n][r] = 0.f;

    const float scale = 0.125f;   // 1/sqrt(64)
    const int KT = (L_ + 63) >> 6; // 33

    for (int kt = 0; kt < KT; kt++) {
        const int k0 = kt * 64;
        // ---- stage K, V tiles (64x64) hi/lo ----
#pragma unroll
        for (int i = 0; i < 4; i++) {
            int f = tid + i * 256;
            int r = f >> 4;
            int d4 = (f & 15) * 4;
            float4 kv = make_float4(0.f, 0.f, 0.f, 0.f);
            float4 vv = make_float4(0.f, 0.f, 0.f, 0.f);
            if (k0 + r < L_) {
                kv = *(const float4*)&Kp[(size_t)(k0 + r) * D_ + d4];
                vv = *(const float4*)&Vp[(size_t)(k0 + r) * D_ + d4];
            }
            uint32_t h, l;
            tf32_split(kv.x, &h, &l); Ks_hi[r * AT_KS_STRIDE + d4 + 0] = h; Ks_lo[r * AT_KS_STRIDE + d4 + 0] = l;
            tf32_split(kv.y, &h, &l); Ks_hi[r * AT_KS_STRIDE + d4 + 1] = h; Ks_lo[r * AT_KS_STRIDE + d4 + 1] = l;
            tf32_split(kv.z, &h, &l); Ks_hi[r * AT_KS_STRIDE + d4 + 2] = h; Ks_lo[r * AT_KS_STRIDE + d4 + 2] = l;
            tf32_split(kv.w, &h, &l); Ks_hi[r * AT_KS_STRIDE + d4 + 3] = h; Ks_lo[r * AT_KS_STRIDE + d4 + 3] = l;
            tf32_split(vv.x, &h, &l); Vs_hi[r * AT_VS_STRIDE + d4 + 0] = h; Vs_lo[r * AT_VS_STRIDE + d4 + 0] = l;
            tf32_split(vv.y, &h, &l); Vs_hi[r * AT_VS_STRIDE + d4 + 1] = h; Vs_lo[r * AT_VS_STRIDE + d4 + 1] = l;
            tf32_split(vv.z, &h, &l); Vs_hi[r * AT_VS_STRIDE + d4 + 2] = h; Vs_lo[r * AT_VS_STRIDE + d4 + 2] = l;
            tf32_split(vv.w, &h, &l); Vs_hi[r * AT_VS_STRIDE + d4 + 3] = h; Vs_lo[r * AT_VS_STRIDE + d4 + 3] = l;
        }
        __syncthreads();

        // ---- S = Q K^T : 3xTF32 ----
        float sacc[8][4];
#pragma unroll
        for (int n = 0; n < 8; n++)
#pragma unroll
            for (int r = 0; r < 4; r++) sacc[n][r] = 0.f;

#pragma unroll
        for (int kk = 0; kk < 8; kk++) {
#pragma unroll
            for (int n = 0; n < 8; n++) {
                uint32_t bh_[2], bl_[2];
                bh_[0] = Ks_hi[(8 * n + g) * AT_KS_STRIDE + 8 * kk + t];
                bh_[1] = Ks_hi[(8 * n + g) * AT_KS_STRIDE + 8 * kk + t + 4];
                bl_[0] = Ks_lo[(8 * n + g) * AT_KS_STRIDE + 8 * kk + t];
                bl_[1] = Ks_lo[(8 * n + g) * AT_KS_STRIDE + 8 * kk + t + 4];
                mma_tf32(sacc[n], ql[kk], bh_, sacc[n]);
                mma_tf32(sacc[n], qh[kk], bl_, sacc[n]);
                mma_tf32(sacc[n], qh[kk], bh_, sacc[n]);
            }
        }

        // ---- scale + mask ----
        const bool partial = (k0 + 64 > L_);
#pragma unroll
        for (int n = 0; n < 8; n++) {
            int c0 = k0 + 8 * n + 2 * t;
            float v0 = sacc[n][0] * scale;
            float v1 = sacc[n][1] * scale;
            float v2 = sacc[n][2] * scale;
            float v3 = sacc[n][3] * scale;
            if (partial) {
                if (c0 >= L_)     { v0 = -1e30f; v2 = -1e30f; }
                if (c0 + 1 >= L_) { v1 = -1e30f; v3 = -1e30f; }
            }
            sacc[n][0] = v0; sacc[n][1] = v1; sacc[n][2] = v2; sacc[n][3] = v3;
        }

        // ---- row max (warp-local quad reduce) ----
        float mx0 = -1e30f, mx1 = -1e30f;
#pragma unroll
        for (int n = 0; n < 8; n++) {
            mx0 = fmaxf(mx0, fmaxf(sacc[n][0], sacc[n][1]));
            mx1 = fmaxf(mx1, fmaxf(sacc[n][2], sacc[n][3]));
        }
        mx0 = fmaxf(mx0, __shfl_xor_sync(0xffffffffu, mx0, 1));
        mx0 = fmaxf(mx0, __shfl_xor_sync(0xffffffffu, mx0, 2));
        mx1 = fmaxf(mx1, __shfl_xor_sync(0xffffffffu, mx1, 1));
        mx1 = fmaxf(mx1, __shfl_xor_sync(0xffffffffu, mx1, 2));

        float mn0 = fmaxf(m0r, mx0);
        float mn1 = fmaxf(m1r, mx1);
        float corr0 = __expf(m0r - mn0);
        float corr1 = __expf(m1r - mn1);
        m0r = mn0; m1r = mn1;

        // ---- exponentiate + row sum ----
        float s0 = 0.f, s1 = 0.f;
#pragma unroll
        for (int n = 0; n < 8; n++) {
            float p0 = __expf(sacc[n][0] - mn0);
            float p1 = __expf(sacc[n][1] - mn0);
            float p2 = __expf(sacc[n][2] - mn1);
            float p3 = __expf(sacc[n][3] - mn1);
            sacc[n][0] = p0; sacc[n][1] = p1; sacc[n][2] = p2; sacc[n][3] = p3;
            s0 += p0 + p1;
            s1 += p2 + p3;
        }
        s0 += __shfl_xor_sync(0xffffffffu, s0, 1);
        s0 += __shfl_xor_sync(0xffffffffu, s0, 2);
        s1 += __shfl_xor_sync(0xffffffffu, s1, 1);
        s1 += __shfl_xor_sync(0xffffffffu, s1, 2);
        l0 = l0 * corr0 + s0;
        l1 = l1 * corr1 + s1;

        // ---- rescale O accum ----
#pragma unroll
        for (int n = 0; n < 8; n++) {
            oacc[n][0] *= corr0; oacc[n][1] *= corr0;
            oacc[n][2] *= corr1; oacc[n][3] *= corr1;
        }

        // ---- write P tile hi/lo into Ps (warp-private rows) ----
#pragma unroll
        for (int n = 0; n < 8; n++) {
            uint32_t h, l;
            tf32_split(sacc[n][0], &h, &l);
            Ps_hi[(wrow + g) * AT_PS_STRIDE + 8 * n + 2 * t]     = h;
            Ps_lo[(wrow + g) * AT_PS_STRIDE + 8 * n + 2 * t]     = l;
            tf32_split(sacc[n][1], &h, &l);
            Ps_hi[(wrow + g) * AT_PS_STRIDE + 8 * n + 2 * t + 1] = h;
            Ps_lo[(wrow + g) * AT_PS_STRIDE + 8 * n + 2 * t + 1] = l;
            tf32_split(sacc[n][2], &h, &l);
            Ps_hi[(wrow + g + 8) * AT_PS_STRIDE + 8 * n + 2 * t]     = h;
            Ps_lo[(wrow + g + 8) * AT_PS_STRIDE + 8 * n + 2 * t]     = l;
            tf32_split(sacc[n][3], &h, &l);
            Ps_hi[(wrow + g + 8) * AT_PS_STRIDE + 8 * n + 2 * t + 1] = h;
            Ps_lo[(wrow + g + 8) * AT_PS_STRIDE + 8 * n + 2 * t + 1] = l;
        }
        __syncwarp();

        // ---- O += P @ V : 3xTF32 ----
#pragma unroll
        for (int kk = 0; kk < 8; kk++) {
            uint32_t ah[4], al_[4];
            ah[0]  = Ps_hi[(wrow + g)     * AT_PS_STRIDE + 8 * kk + t];
            ah[1]  = Ps_hi[(wrow + g + 8) * AT_PS_STRIDE + 8 * kk + t];
            ah[2]  = Ps_hi[(wrow + g)     * AT_PS_STRIDE + 8 * kk + t + 4];
            ah[3]  = Ps_hi[(wrow + g + 8) * AT_PS_STRIDE + 8 * kk + t + 4];
            al_[0] = Ps_lo[(wrow + g)     * AT_PS_STRIDE + 8 * kk + t];
            al_[1] = Ps_lo[(wrow + g + 8) * AT_PS_STRIDE + 8 * kk + t];
            al_[2] = Ps_lo[(wrow + g)     * AT_PS_STRIDE + 8 * kk + t + 4];
            al_[3] = Ps_lo[(wrow + g + 8) * AT_PS_STRIDE + 8 * kk + t + 4];
#pragma unroll
            for (int n = 0; n < 8; n++) {
                uint32_t bh_[2], bl_[2];
                bh_[0] = Vs_hi[(8 * kk + t)     * AT_VS_STRIDE + 8 * n + g];
                bh_[1] = Vs_hi[(8 * kk + t + 4) * AT_VS_STRIDE + 8 * n + g];
                bl_[0] = Vs_lo[(8 * kk + t)     * AT_VS_STRIDE + 8 * n + g];
                bl_[1] = Vs_lo[(8 * kk + t + 4) * AT_VS_STRIDE + 8 * n + g];
                mma_tf32(oacc[n], al_, bh_, oacc[n]);
                mma_tf32(oacc[n], ah,  bl_, oacc[n]);
                mma_tf32(oacc[n], ah,  bh_, oacc[n]);
            }
        }
        __syncthreads();   // before next K/V staging overwrites tiles
    }

    // ---- epilogue: normalize, write (B,L,C) ----
    const int bb = bh >> 4;
    const int h = bh & (H_ - 1);
    const int r0 = q0 + wrow + g;
    const int r1 = r0 + 8;
    float inv0 = (l0 > 0.f) ? 1.0f / l0 : 0.f;
    float inv1 = (l1 > 0.f) ? 1.0f / l1 : 0.f;
#pragma unroll
    for (int n = 0; n < 8; n++) {
        int d0 = 8 * n + 2 * t;
        if (r0 < L_) {
            float2 o = make_float2(oacc[n][0] * inv0, oacc[n][1] * inv0);
            *(float2*)&Out[((size_t)(bb * L_ + r0)) * C_ + h * D_ + d0] = o;
        }
        if (r1 < L_) {
            float2 o = make_float2(oacc[n][2] * inv1, oacc[n][3] * inv1);
            *(float2*)&Out[((size_t)(bb * L_ + r1)) * C_ + h * D_ + d0] = o;
        }
    }
}

// =====================================================================
// LayerNorm over last dim (1024). One block (256 threads) per row.
// =====================================================================
__global__ __launch_bounds__(256) void ln_kernel(
    const float* __restrict__ in, const float* __restrict__ gamma,
    const float* __restrict__ beta, float* __restrict__ out)
{
    __shared__ float red[16];
    const int row = blockIdx.x;
    const float* xp = in + (size_t)row * C_;
    const int c = threadIdx.x * 4;

    float4 v = *(const float4*)&xp[c];
    float s  = v.x + v.y + v.z + v.w;
    float sq = v.x * v.x + v.y * v.y + v.z * v.z + v.w * v.w;

#pragma unroll
    for (int off = 16; off > 0; off >>= 1) {
        s  += __shfl_xor_sync(0xffffffffu, s, off);
        sq += __shfl_xor_sync(0xffffffffu, sq, off);
    }
    int wid = threadIdx.x >> 5, lid = threadIdx.x & 31;
    if (lid == 0) { red[wid] = s; red[8 + wid] = sq; }
    __syncthreads();

    float ts = 0.f, tq = 0.f;
#pragma unroll
    for (int i = 0; i < 8; i++) { ts += red[i]; tq += red[8 + i]; }

    float mu   = ts * (1.0f / C_);
    float var  = tq * (1.0f / C_) - mu * mu;
    float rstd = rsqrtf(var + 1e-5f);

    float4 g = *(const float4*)&gamma[c];
    float4 b = *(const float4*)&beta[c];
    float4 o;
    o.x = (v.x - mu) * rstd * g.x + b.x;
    o.y = (v.y - mu) * rstd * g.y + b.y;
    o.z = (v.z - mu) * rstd * g.z + b.z;
    o.w = (v.w - mu) * rstd * g.w + b.w;
    *(float4*)&out[(size_t)row * C_ + c] = o;
}

// =====================================================================
// host side
// =====================================================================
static float* sym_addr_qkv()  { void* p = 0; cudaGetSymbolAddress(&p, g_qkv);  return (float*)p; }
static float* sym_addr_q()    { void* p = 0; cudaGetSymbolAddress(&p, g_q);    return (float*)p; }
static float* sym_addr_k()    { void* p = 0; cudaGetSymbolAddress(&p, g_k);    return (float*)p; }
static float* sym_addr_v()    { void* p = 0; cudaGetSymbolAddress(&p, g_v);    return (float*)p; }
static float* sym_addr_attn() { void* p = 0; cudaGetSymbolAddress(&p, g_attn); return (float*)p; }
static float* sym_addr_ln()   { void* p = 0; cudaGetSymbolAddress(&p, g_ln);   return (float*)p; }

extern "C" void kernel_launch(void* const* d_in, const int* in_sizes, int n_in,
                              void* d_out, int out_size)
{
    const float* x     = (const float*)d_in[0];
    const float* rope  = (const float*)d_in[1];
    const float* Wqkv  = (const float*)d_in[2];
    const float* bqkv  = (const float*)d_in[3];
    const float* Wproj = (const float*)d_in[4];
    const float* bproj = (const float*)d_in[5];
    const float* gamma = (const float*)d_in[6];
    const float* beta  = (const float*)d_in[7];
    float* out = (float*)d_out;

    float* qkv = sym_addr_qkv();
    float* q   = sym_addr_q();
    float* k   = sym_addr_k();
    float* v   = sym_addr_v();
    float* att = sym_addr_attn();
    float* ln  = sym_addr_ln();

    const int attn_smem = AT_SMEM_U32 * 4;   // 141312 bytes
    cudaFuncSetAttribute(attn_tc_kernel,
                         cudaFuncAttributeMaxDynamicSharedMemorySize, attn_smem);
    cudaFuncSetAttribute(gemm_tf32x3_bias_kernel,
                         cudaFuncAttributeMaxDynamicSharedMemorySize, G_SMEM_BYTES);

    // 1) QKV GEMM (3xTF32 tensor core)
    {
        dim3 grid(3 * C_ / 128, (M_ + 127) / 128);
        gemm_tf32x3_bias_kernel<<<grid, 256, G_SMEM_BYTES>>>(x, Wqkv, bqkv, qkv, M_, 3 * C_, C_);
    }
    // 2) RoPE + split into (B,H,L,D)
    {
        int total = B_ * H_ * L_ * 32;
        rope_split_kernel<<<(total + 255) / 256, 256>>>(qkv, rope);
    }
    // 3) Flash attention (3xTF32 tensor core)
    {
        dim3 grid((L_ + 127) / 128, B_ * H_);
        attn_tc_kernel<<<grid, 256, attn_smem>>>(q, k, v, att);
    }
    // 4) LayerNorm
    ln_kernel<<<M_, 256>>>(att, gamma, beta, ln);
    // 5) Proj GEMM (3xTF32 tensor core)
    {
        dim3 grid(C_ / 128, (M_ + 127) / 128);
        gemm_tf32x3_bias_kernel<<<grid, 256, G_SMEM_BYTES>>>(ln, Wproj, bproj, out, M_, C_, C_);
    }
}

// round 13
// speedup vs baseline: 2.1788x; 1.6736x over previous
#include <cuda_runtime.h>
#include <cuda_bf16.h>
#include <math.h>
#include <stdint.h>

// Problem constants
#define B_    4
#define L_    2052
#define C_    1024
#define H_    16
#define D_    64
#define NREG_ 4
#define M_    (B_ * L_)      // 8208 rows
#define LP_   (L_ - NREG_)   // 2048 rope positions

// ---------------- scratch (device globals, no allocations) ----------------
__device__ float g_qkv[M_ * 3 * C_];
__device__ float g_q[B_ * H_ * L_ * D_];
__device__ float g_k[B_ * H_ * L_ * D_];
__device__ float g_v[B_ * H_ * L_ * D_];
__device__ float g_attn[M_ * C_];
__device__ float g_ln[M_ * C_];

// ---------------- bf16 helpers ----------------
__device__ __forceinline__ uint32_t packbf2(__nv_bfloat16 a, __nv_bfloat16 b) {
    __nv_bfloat162 t = __halves2bfloat162(a, b);   // .x = a (low half)
    return *(uint32_t*)&t;
}

// 2-way bf16 split of a pair (x0 -> low half, x1 -> high half).
__device__ __forceinline__ void bf16_split2(float x0, float x1,
                                            uint32_t* hi, uint32_t* lo) {
    __nv_bfloat16 h0 = __float2bfloat16(x0);
    __nv_bfloat16 h1 = __float2bfloat16(x1);
    float r0 = x0 - __bfloat162float(h0);
    float r1 = x1 - __bfloat162float(h1);
    *hi = packbf2(h0, h1);
    *lo = packbf2(__float2bfloat16(r0), __float2bfloat16(r1));
}

__device__ __forceinline__ void mma_bf16(float* d, const uint32_t* a,
                                         const uint32_t* b, const float* c) {
    asm volatile(
        "mma.sync.aligned.m16n8k16.row.col.f32.bf16.bf16.f32 "
        "{%0,%1,%2,%3}, {%4,%5,%6,%7}, {%8,%9}, {%10,%11,%12,%13};\n"
        : "=f"(d[0]), "=f"(d[1]), "=f"(d[2]), "=f"(d[3])
        : "r"(a[0]), "r"(a[1]), "r"(a[2]), "r"(a[3]),
          "r"(b[0]), "r"(b[1]),
          "f"(c[0]), "f"(c[1]), "f"(c[2]), "f"(c[3]));
}

// =====================================================================
// 3-term split-bf16 GEMM with bias: C[M,N] = A[M,K] @ B[K,N] + bias[N]
// 128x128 block tile, BK=32, 256 threads (8 warps, 2x4), warp tile 64x32.
// A words: (row, kpair) stride 20. B words: (kpair, n) stride 132
// (word packs k and k+1). All fragment reads bank-conflict-free.
// =====================================================================
#define GA_STR 20
#define GB_STR 132

__global__ __launch_bounds__(256) void gemm_bf16x3_bias_kernel(
    const float* __restrict__ A, const float* __restrict__ Bm,
    const float* __restrict__ bias, float* __restrict__ Cm,
    int M, int N, int K)
{
    __shared__ uint32_t As_hi[128 * GA_STR];
    __shared__ uint32_t As_lo[128 * GA_STR];
    __shared__ uint32_t Bs_hi[16 * GB_STR];
    __shared__ uint32_t Bs_lo[16 * GB_STR];

    const int tid  = threadIdx.x;
    const int lane = tid & 31;
    const int warp = tid >> 5;
    const int wm   = warp & 1;
    const int wn   = warp >> 1;
    const int g    = lane >> 2;
    const int t    = lane & 3;
    const int m0   = blockIdx.y * 128;
    const int n0   = blockIdx.x * 128;

    float acc[4][4][4];
#pragma unroll
    for (int i = 0; i < 4; i++)
#pragma unroll
        for (int j = 0; j < 4; j++)
#pragma unroll
            for (int r = 0; r < 4; r++) acc[i][j][r] = 0.0f;

    for (int k0 = 0; k0 < K; k0 += 32) {
        // ---- stage A (128x32): pairs along k within a row ----
#pragma unroll
        for (int i = 0; i < 4; i++) {
            int f  = tid + i * 256;        // 0..1023
            int r  = f >> 3;               // 0..127
            int c4 = (f & 7) * 4;          // 0..28
            float4 v = make_float4(0.f, 0.f, 0.f, 0.f);
            if (m0 + r < M) v = *(const float4*)&A[(size_t)(m0 + r) * K + k0 + c4];
            uint32_t h, l;
            int w = r * GA_STR + (c4 >> 1);
            bf16_split2(v.x, v.y, &h, &l); As_hi[w]     = h; As_lo[w]     = l;
            bf16_split2(v.z, v.w, &h, &l); As_hi[w + 1] = h; As_lo[w + 1] = l;
        }
        // ---- stage B (32x128): word packs rows k,k+1 for one n ----
#pragma unroll
        for (int i = 0; i < 2; i++) {
            int f  = tid + i * 256;        // 0..511
            int kp = f >> 5;               // 0..15
            int n4 = (f & 31) * 4;         // 0..124
            float4 va = *(const float4*)&Bm[(size_t)(k0 + 2 * kp)     * N + n0 + n4];
            float4 vb = *(const float4*)&Bm[(size_t)(k0 + 2 * kp + 1) * N + n0 + n4];
            uint32_t h0, l0, h1, l1, h2, l2, h3, l3;
            bf16_split2(va.x, vb.x, &h0, &l0);
            bf16_split2(va.y, vb.y, &h1, &l1);
            bf16_split2(va.z, vb.z, &h2, &l2);
            bf16_split2(va.w, vb.w, &h3, &l3);
            int w = kp * GB_STR + n4;
            *(uint4*)&Bs_hi[w] = make_uint4(h0, h1, h2, h3);
            *(uint4*)&Bs_lo[w] = make_uint4(l0, l1, l2, l3);
        }
        __syncthreads();

#pragma unroll
        for (int kk2 = 0; kk2 < 16; kk2 += 8) {   // kpair base: 0, 8
            uint32_t ah[4][4], al[4][4], bh[4][2], bl[4][2];
#pragma unroll
            for (int i = 0; i < 4; i++) {
                int rb = wm * 64 + i * 16;
                ah[i][0] = As_hi[(rb + g)     * GA_STR + kk2 + t];
                ah[i][1] = As_hi[(rb + g + 8) * GA_STR + kk2 + t];
                ah[i][2] = As_hi[(rb + g)     * GA_STR + kk2 + t + 4];
                ah[i][3] = As_hi[(rb + g + 8) * GA_STR + kk2 + t + 4];
                al[i][0] = As_lo[(rb + g)     * GA_STR + kk2 + t];
                al[i][1] = As_lo[(rb + g + 8) * GA_STR + kk2 + t];
                al[i][2] = As_lo[(rb + g)     * GA_STR + kk2 + t + 4];
                al[i][3] = As_lo[(rb + g + 8) * GA_STR + kk2 + t + 4];
            }
#pragma unroll
            for (int j = 0; j < 4; j++) {
                int nb = wn * 32 + j * 8;
                bh[j][0] = Bs_hi[(kk2 + t)     * GB_STR + nb + g];
                bh[j][1] = Bs_hi[(kk2 + t + 4) * GB_STR + nb + g];
                bl[j][0] = Bs_lo[(kk2 + t)     * GB_STR + nb + g];
                bl[j][1] = Bs_lo[(kk2 + t + 4) * GB_STR + nb + g];
            }
#pragma unroll
            for (int i = 0; i < 4; i++)
#pragma unroll
                for (int j = 0; j < 4; j++) {
                    mma_bf16(acc[i][j], al[i], bh[j], acc[i][j]);
                    mma_bf16(acc[i][j], ah[i], bl[j], acc[i][j]);
                    mma_bf16(acc[i][j], ah[i], bh[j], acc[i][j]);
                }
        }
        __syncthreads();
    }

#pragma unroll
    for (int i = 0; i < 4; i++) {
        int row0 = m0 + wm * 64 + i * 16 + g;
#pragma unroll
        for (int j = 0; j < 4; j++) {
            int col = n0 + wn * 32 + j * 8 + 2 * t;
            float b0 = bias[col], b1 = bias[col + 1];
            if (row0 < M) {
                float2 o = make_float2(acc[i][j][0] + b0, acc[i][j][1] + b1);
                *(float2*)&Cm[(size_t)row0 * N + col] = o;
            }
            if (row0 + 8 < M) {
                float2 o = make_float2(acc[i][j][2] + b0, acc[i][j][3] + b1);
                *(float2*)&Cm[(size_t)(row0 + 8) * N + col] = o;
            }
        }
    }
}

// =====================================================================
// RoPE + split qkv -> g_q, g_k, g_v in (B,H,L,D) layout.
// =====================================================================
__global__ __launch_bounds__(256) void rope_split_kernel(
    const float* __restrict__ qkv, const float* __restrict__ rope)
{
    int idx = blockIdx.x * blockDim.x + threadIdx.x;
    const int total = B_ * H_ * L_ * 32;
    if (idx >= total) return;

    int dp = idx & 31;
    int t  = idx >> 5;
    int l  = t % L_;
    int bh = t / L_;
    int h  = bh & (H_ - 1);
    int bb = bh >> 4;

    size_t base = ((size_t)(bb * L_ + l)) * (3 * C_) + h * D_;
    float q1 = qkv[base + dp],          q2 = qkv[base + dp + 32];
    float k1 = qkv[base + C_ + dp],     k2 = qkv[base + C_ + dp + 32];
    float v1 = qkv[base + 2 * C_ + dp], v2 = qkv[base + 2 * C_ + dp + 32];

    if (l >= NREG_) {
        int p = l - NREG_;
        const float* cosr = rope + (size_t)p * D_;
        const float* sinr = rope + (size_t)LP_ * D_ + (size_t)p * D_;
        float c1 = cosr[dp], c2 = cosr[dp + 32];
        float s1 = sinr[dp], s2 = sinr[dp + 32];
        float nq1 = q1 * c1 - q2 * s1;
        float nq2 = q2 * c2 + q1 * s2;
        float nk1 = k1 * c1 - k2 * s1;
        float nk2 = k2 * c2 + k1 * s2;
        q1 = nq1; q2 = nq2; k1 = nk1; k2 = nk2;
    }

    size_t dst = ((size_t)bh * L_ + l) * D_;
    g_q[dst + dp] = q1; g_q[dst + dp + 32] = q2;
    g_k[dst + dp] = k1; g_k[dst + dp + 32] = k2;
    g_v[dst + dp] = v1; g_v[dst + dp + 32] = v2;
}

// =====================================================================
// Flash attention, 3-term split-bf16 tensor cores.
// Block: 128 q-rows x one (b,h). 8 warps, each owns m16 strip.
// smem words (hi/lo pairs):
//   Ks [64 rows][36]  (kpair words along d)
//   Vs [32 keypairs][72]  (word packs keys 2k,2k+1 for one d)
//   Ps [128 rows][36] (Q staging then P tiles; kpair words)
// Total 73728 bytes dynamic.
// =====================================================================
#define AT_KS_STR 36
#define AT_VS_STR 72
#define AT_PS_STR 36
#define AT_SMEM_U32 (2 * (64 * AT_KS_STR + 32 * AT_VS_STR + 128 * AT_PS_STR))

__global__ __launch_bounds__(256) void attn_tc_kernel(
    const float* __restrict__ Q, const float* __restrict__ K,
    const float* __restrict__ V, float* __restrict__ Out)
{
    extern __shared__ uint32_t sm[];
    uint32_t* Ks_hi = sm;
    uint32_t* Ks_lo = Ks_hi + 64 * AT_KS_STR;
    uint32_t* Vs_hi = Ks_lo + 64 * AT_KS_STR;
    uint32_t* Vs_lo = Vs_hi + 32 * AT_VS_STR;
    uint32_t* Ps_hi = Vs_lo + 32 * AT_VS_STR;
    uint32_t* Ps_lo = Ps_hi + 128 * AT_PS_STR;

    const int bh = blockIdx.y;
    const int q0 = blockIdx.x * 128;
    const float* Qp = Q + (size_t)bh * L_ * D_;
    const float* Kp = K + (size_t)bh * L_ * D_;
    const float* Vp = V + (size_t)bh * L_ * D_;

    const int tid  = threadIdx.x;
    const int lane = tid & 31;
    const int warp = tid >> 5;
    const int g    = lane >> 2;
    const int t    = lane & 3;
    const int wrow = warp * 16;

    // ---- stage Q (128x64) hi/lo into Ps (kpair words per row) ----
#pragma unroll
    for (int i = 0; i < 8; i++) {
        int f = tid + i * 256;
        int r = f >> 4;
        int d4 = (f & 15) * 4;
        float4 v = make_float4(0.f, 0.f, 0.f, 0.f);
        if (q0 + r < L_) v = *(const float4*)&Qp[(size_t)(q0 + r) * D_ + d4];
        uint32_t h, l;
        int w = r * AT_PS_STR + (d4 >> 1);
        bf16_split2(v.x, v.y, &h, &l); Ps_hi[w]     = h; Ps_lo[w]     = l;
        bf16_split2(v.z, v.w, &h, &l); Ps_hi[w + 1] = h; Ps_lo[w + 1] = l;
    }
    __syncthreads();

    // ---- preload Q fragments hi/lo (4 k16-steps) ----
    uint32_t qh[4][4], ql[4][4];
#pragma unroll
    for (int kk = 0; kk < 4; kk++) {
        int base = 8 * kk;
        qh[kk][0] = Ps_hi[(wrow + g)     * AT_PS_STR + base + t];
        qh[kk][1] = Ps_hi[(wrow + g + 8) * AT_PS_STR + base + t];
        qh[kk][2] = Ps_hi[(wrow + g)     * AT_PS_STR + base + t + 4];
        qh[kk][3] = Ps_hi[(wrow + g + 8) * AT_PS_STR + base + t + 4];
        ql[kk][0] = Ps_lo[(wrow + g)     * AT_PS_STR + base + t];
        ql[kk][1] = Ps_lo[(wrow + g + 8) * AT_PS_STR + base + t];
        ql[kk][2] = Ps_lo[(wrow + g)     * AT_PS_STR + base + t + 4];
        ql[kk][3] = Ps_lo[(wrow + g + 8) * AT_PS_STR + base + t + 4];
    }
    __syncthreads();   // Ps free for P tiles

    float m0r = -1e30f, m1r = -1e30f, l0 = 0.f, l1 = 0.f;
    float oacc[8][4];
#pragma unroll
    for (int n = 0; n < 8; n++)
#pragma unroll
        for (int r = 0; r < 4; r++) oacc[n][r] = 0.f;

    const float scale = 0.125f;    // 1/sqrt(64)
    const int KT = (L_ + 63) >> 6; // 33

    for (int kt = 0; kt < KT; kt++) {
        const int k0 = kt * 64;
        // ---- stage K (64x64): kpair words along d ----
#pragma unroll
        for (int i = 0; i < 4; i++) {
            int f = tid + i * 256;       // 0..1023
            int r = f >> 4;              // 0..63
            int d4 = (f & 15) * 4;
            float4 kv = make_float4(0.f, 0.f, 0.f, 0.f);
            if (k0 + r < L_) kv = *(const float4*)&Kp[(size_t)(k0 + r) * D_ + d4];
            uint32_t h, l;
            int w = r * AT_KS_STR + (d4 >> 1);
            bf16_split2(kv.x, kv.y, &h, &l); Ks_hi[w]     = h; Ks_lo[w]     = l;
            bf16_split2(kv.z, kv.w, &h, &l); Ks_hi[w + 1] = h; Ks_lo[w + 1] = l;
        }
        // ---- stage V (64x64): word packs keys 2kp,2kp+1 for one d ----
#pragma unroll
        for (int i = 0; i < 2; i++) {
            int f = tid + i * 256;       // 0..511
            int kp = f >> 4;             // 0..31
            int d4 = (f & 15) * 4;       // 0..60
            float4 va = make_float4(0.f, 0.f, 0.f, 0.f);
            float4 vb = make_float4(0.f, 0.f, 0.f, 0.f);
            if (k0 + 2 * kp < L_)     va = *(const float4*)&Vp[(size_t)(k0 + 2 * kp)     * D_ + d4];
            if (k0 + 2 * kp + 1 < L_) vb = *(const float4*)&Vp[(size_t)(k0 + 2 * kp + 1) * D_ + d4];
            uint32_t h0, l0_, h1, l1_, h2, l2_, h3, l3_;
            bf16_split2(va.x, vb.x, &h0, &l0_);
            bf16_split2(va.y, vb.y, &h1, &l1_);
            bf16_split2(va.z, vb.z, &h2, &l2_);
            bf16_split2(va.w, vb.w, &h3, &l3_);
            int w = kp * AT_VS_STR + d4;
            *(uint4*)&Vs_hi[w] = make_uint4(h0, h1, h2, h3);
            *(uint4*)&Vs_lo[w] = make_uint4(l0_, l1_, l2_, l3_);
        }
        __syncthreads();

        // ---- S = Q K^T : m16 x n64, 4 k16-steps, 3-term ----
        float sacc[8][4];
#pragma unroll
        for (int n = 0; n < 8; n++)
#pragma unroll
            for (int r = 0; r < 4; r++) sacc[n][r] = 0.f;

#pragma unroll
        for (int kk = 0; kk < 4; kk++) {
            int base = 8 * kk;
#pragma unroll
            for (int n = 0; n < 8; n++) {
                uint32_t bh_[2], bl_[2];
                bh_[0] = Ks_hi[(8 * n + g) * AT_KS_STR + base + t];
                bh_[1] = Ks_hi[(8 * n + g) * AT_KS_STR + base + t + 4];
                bl_[0] = Ks_lo[(8 * n + g) * AT_KS_STR + base + t];
                bl_[1] = Ks_lo[(8 * n + g) * AT_KS_STR + base + t + 4];
                mma_bf16(sacc[n], ql[kk], bh_, sacc[n]);
                mma_bf16(sacc[n], qh[kk], bl_, sacc[n]);
                mma_bf16(sacc[n], qh[kk], bh_, sacc[n]);
            }
        }

        // ---- scale + mask ----
        const bool partial = (k0 + 64 > L_);
#pragma unroll
        for (int n = 0; n < 8; n++) {
            int c0 = k0 + 8 * n + 2 * t;
            float v0 = sacc[n][0] * scale;
            float v1 = sacc[n][1] * scale;
            float v2 = sacc[n][2] * scale;
            float v3 = sacc[n][3] * scale;
            if (partial) {
                if (c0 >= L_)     { v0 = -1e30f; v2 = -1e30f; }
                if (c0 + 1 >= L_) { v1 = -1e30f; v3 = -1e30f; }
            }
            sacc[n][0] = v0; sacc[n][1] = v1; sacc[n][2] = v2; sacc[n][3] = v3;
        }

        // ---- row max (warp-local quad reduce) ----
        float mx0 = -1e30f, mx1 = -1e30f;
#pragma unroll
        for (int n = 0; n < 8; n++) {
            mx0 = fmaxf(mx0, fmaxf(sacc[n][0], sacc[n][1]));
            mx1 = fmaxf(mx1, fmaxf(sacc[n][2], sacc[n][3]));
        }
        mx0 = fmaxf(mx0, __shfl_xor_sync(0xffffffffu, mx0, 1));
        mx0 = fmaxf(mx0, __shfl_xor_sync(0xffffffffu, mx0, 2));
        mx1 = fmaxf(mx1, __shfl_xor_sync(0xffffffffu, mx1, 1));
        mx1 = fmaxf(mx1, __shfl_xor_sync(0xffffffffu, mx1, 2));

        float mn0 = fmaxf(m0r, mx0);
        float mn1 = fmaxf(m1r, mx1);
        float corr0 = __expf(m0r - mn0);
        float corr1 = __expf(m1r - mn1);
        m0r = mn0; m1r = mn1;

        // ---- exponentiate + row sum ----
        float s0 = 0.f, s1 = 0.f;
#pragma unroll
        for (int n = 0; n < 8; n++) {
            float p0 = __expf(sacc[n][0] - mn0);
            float p1 = __expf(sacc[n][1] - mn0);
            float p2 = __expf(sacc[n][2] - mn1);
            float p3 = __expf(sacc[n][3] - mn1);
            sacc[n][0] = p0; sacc[n][1] = p1; sacc[n][2] = p2; sacc[n][3] = p3;
            s0 += p0 + p1;
            s1 += p2 + p3;
        }
        s0 += __shfl_xor_sync(0xffffffffu, s0, 1);
        s0 += __shfl_xor_sync(0xffffffffu, s0, 2);
        s1 += __shfl_xor_sync(0xffffffffu, s1, 1);
        s1 += __shfl_xor_sync(0xffffffffu, s1, 2);
        l0 = l0 * corr0 + s0;
        l1 = l1 * corr1 + s1;

        // ---- rescale O accum ----
#pragma unroll
        for (int n = 0; n < 8; n++) {
            oacc[n][0] *= corr0; oacc[n][1] *= corr0;
            oacc[n][2] *= corr1; oacc[n][3] *= corr1;
        }

        // ---- write P tile hi/lo into Ps: C cols (2t,2t+1) = one kpair word ----
#pragma unroll
        for (int n = 0; n < 8; n++) {
            uint32_t h, l;
            bf16_split2(sacc[n][0], sacc[n][1], &h, &l);
            Ps_hi[(wrow + g) * AT_PS_STR + 4 * n + t] = h;
            Ps_lo[(wrow + g) * AT_PS_STR + 4 * n + t] = l;
            bf16_split2(sacc[n][2], sacc[n][3], &h, &l);
            Ps_hi[(wrow + g + 8) * AT_PS_STR + 4 * n + t] = h;
            Ps_lo[(wrow + g + 8) * AT_PS_STR + 4 * n + t] = l;
        }
        __syncwarp();

        // ---- O += P @ V : 4 k16-steps over keys, 3-term ----
#pragma unroll
        for (int kk = 0; kk < 4; kk++) {
            int base = 8 * kk;
            uint32_t ah[4], al_[4];
            ah[0]  = Ps_hi[(wrow + g)     * AT_PS_STR + base + t];
            ah[1]  = Ps_hi[(wrow + g + 8) * AT_PS_STR + base + t];
            ah[2]  = Ps_hi[(wrow + g)     * AT_PS_STR + base + t + 4];
            ah[3]  = Ps_hi[(wrow + g + 8) * AT_PS_STR + base + t + 4];
            al_[0] = Ps_lo[(wrow + g)     * AT_PS_STR + base + t];
            al_[1] = Ps_lo[(wrow + g + 8) * AT_PS_STR + base + t];
            al_[2] = Ps_lo[(wrow + g)     * AT_PS_STR + base + t + 4];
            al_[3] = Ps_lo[(wrow + g + 8) * AT_PS_STR + base + t + 4];
#pragma unroll
            for (int n = 0; n < 8; n++) {
                uint32_t bh_[2], bl_[2];
                bh_[0] = Vs_hi[(base + t)     * AT_VS_STR + 8 * n + g];
                bh_[1] = Vs_hi[(base + t + 4) * AT_VS_STR + 8 * n + g];
                bl_[0] = Vs_lo[(base + t)     * AT_VS_STR + 8 * n + g];
                bl_[1] = Vs_lo[(base + t + 4) * AT_VS_STR + 8 * n + g];
                mma_bf16(oacc[n], al_, bh_, oacc[n]);
                mma_bf16(oacc[n], ah,  bl_, oacc[n]);
                mma_bf16(oacc[n], ah,  bh_, oacc[n]);
            }
        }
        __syncthreads();   // before next K/V staging overwrites tiles
    }

    // ---- epilogue: normalize, write (B,L,C) ----
    const int bb = bh >> 4;
    const int h = bh & (H_ - 1);
    const int r0 = q0 + wrow + g;
    const int r1 = r0 + 8;
    float inv0 = (l0 > 0.f) ? 1.0f / l0 : 0.f;
    float inv1 = (l1 > 0.f) ? 1.0f / l1 : 0.f;
#pragma unroll
    for (int n = 0; n < 8; n++) {
        int d0 = 8 * n + 2 * t;
        if (r0 < L_) {
            float2 o = make_float2(oacc[n][0] * inv0, oacc[n][1] * inv0);
            *(float2*)&Out[((size_t)(bb * L_ + r0)) * C_ + h * D_ + d0] = o;
        }
        if (r1 < L_) {
            float2 o = make_float2(oacc[n][2] * inv1, oacc[n][3] * inv1);
            *(float2*)&Out[((size_t)(bb * L_ + r1)) * C_ + h * D_ + d0] = o;
        }
    }
}

// =====================================================================
// LayerNorm over last dim (1024). One block (256 threads) per row.
// =====================================================================
__global__ __launch_bounds__(256) void ln_kernel(
    const float* __restrict__ in, const float* __restrict__ gamma,
    const float* __restrict__ beta, float* __restrict__ out)
{
    __shared__ float red[16];
    const int row = blockIdx.x;
    const float* xp = in + (size_t)row * C_;
    const int c = threadIdx.x * 4;

    float4 v = *(const float4*)&xp[c];
    float s  = v.x + v.y + v.z + v.w;
    float sq = v.x * v.x + v.y * v.y + v.z * v.z + v.w * v.w;

#pragma unroll
    for (int off = 16; off > 0; off >>= 1) {
        s  += __shfl_xor_sync(0xffffffffu, s, off);
        sq += __shfl_xor_sync(0xffffffffu, sq, off);
    }
    int wid = threadIdx.x >> 5, lid = threadIdx.x & 31;
    if (lid == 0) { red[wid] = s; red[8 + wid] = sq; }
    __syncthreads();

    float ts = 0.f, tq = 0.f;
#pragma unroll
    for (int i = 0; i < 8; i++) { ts += red[i]; tq += red[8 + i]; }

    float mu   = ts * (1.0f / C_);
    float var  = tq * (1.0f / C_) - mu * mu;
    float rstd = rsqrtf(var + 1e-5f);

    float4 g = *(const float4*)&gamma[c];
    float4 b = *(const float4*)&beta[c];
    float4 o;
    o.x = (v.x - mu) * rstd * g.x + b.x;
    o.y = (v.y - mu) * rstd * g.y + b.y;
    o.z = (v.z - mu) * rstd * g.z + b.z;
    o.w = (v.w - mu) * rstd * g.w + b.w;
    *(float4*)&out[(size_t)row * C_ + c] = o;
}

// =====================================================================
// host side
// =====================================================================
static float* sym_addr_qkv()  { void* p = 0; cudaGetSymbolAddress(&p, g_qkv);  return (float*)p; }
static float* sym_addr_q()    { void* p = 0; cudaGetSymbolAddress(&p, g_q);    return (float*)p; }
static float* sym_addr_k()    { void* p = 0; cudaGetSymbolAddress(&p, g_k);    return (float*)p; }
static float* sym_addr_v()    { void* p = 0; cudaGetSymbolAddress(&p, g_v);    return (float*)p; }
static float* sym_addr_attn() { void* p = 0; cudaGetSymbolAddress(&p, g_attn); return (float*)p; }
static float* sym_addr_ln()   { void* p = 0; cudaGetSymbolAddress(&p, g_ln);   return (float*)p; }

extern "C" void kernel_launch(void* const* d_in, const int* in_sizes, int n_in,
                              void* d_out, int out_size)
{
    const float* x     = (const float*)d_in[0];
    const float* rope  = (const float*)d_in[1];
    const float* Wqkv  = (const float*)d_in[2];
    const float* bqkv  = (const float*)d_in[3];
    const float* Wproj = (const float*)d_in[4];
    const float* bproj = (const float*)d_in[5];
    const float* gamma = (const float*)d_in[6];
    const float* beta  = (const float*)d_in[7];
    float* out = (float*)d_out;

    float* qkv = sym_addr_qkv();
    float* q   = sym_addr_q();
    float* k   = sym_addr_k();
    float* v   = sym_addr_v();
    float* att = sym_addr_attn();
    float* ln  = sym_addr_ln();

    const int attn_smem = AT_SMEM_U32 * 4;   // 73728 bytes
    cudaFuncSetAttribute(attn_tc_kernel,
                         cudaFuncAttributeMaxDynamicSharedMemorySize, attn_smem);

    // 1) QKV GEMM (split-bf16 tensor core)
    {
        dim3 grid(3 * C_ / 128, (M_ + 127) / 128);
        gemm_bf16x3_bias_kernel<<<grid, 256>>>(x, Wqkv, bqkv, qkv, M_, 3 * C_, C_);
    }
    // 2) RoPE + split into (B,H,L,D)
    {
        int total = B_ * H_ * L_ * 32;
        rope_split_kernel<<<(total + 255) / 256, 256>>>(qkv, rope);
    }
    // 3) Flash attention (split-bf16 tensor core)
    {
        dim3 grid((L_ + 127) / 128, B_ * H_);
        attn_tc_kernel<<<grid, 256, attn_smem>>>(q, k, v, att);
    }
    // 4) LayerNorm
    ln_kernel<<<M_, 256>>>(att, gamma, beta, ln);
    // 5) Proj GEMM (split-bf16 tensor core)
    {
        dim3 grid(C_ / 128, (M_ + 127) / 128);
        gemm_bf16x3_bias_kernel<<<grid, 256>>>(ln, Wproj, bproj, out, M_, C_, C_);
    }
}